// round 10
// baseline (speedup 1.0000x reference)
#include <cuda_runtime.h>
#include <cuda_bf16.h>

#define BB 64
#define VV 64
#define TT 256
#define FF 64
#define NT  256
#define BPB 8     // one warp per batch row
#define AP  68    // adj row pitch: 272B, 16B-aligned; LDS.128 conflict-free (68 mod 32 = 4)

// ---------------------------------------------------------------------------
// Fused kernel, warp-owned rows, 8 CTAs/SM occupancy target.
// Block = (bc, t): one timestep, 8 batches. Grid x-major => the 8 blocks of a
// given t are consecutive/co-resident: A[t] hits DRAM once, L2 7x.
//  Stage:  adj = sigmoid(A_t)*(1-I)+I; xs[bl][w] = X[b,w,t]; ONE barrier.
//  Warp wid: dot (LDS.128, conflict-free) -> streams own 16KB row (__stcs).
// ---------------------------------------------------------------------------
__global__ __launch_bounds__(NT, 8)
void gnn_fused(const float* __restrict__ X,
               const float* __restrict__ A,
               const float* __restrict__ W,
               float* __restrict__ out)
{
    __shared__ float adj[VV][AP];       // 17.4 KB
    __shared__ float xs[BPB][VV];       // 2 KB
    __shared__ float hs[BPB][VV];       // 2 KB

    const int bc  = blockIdx.x;         // 0..7   (fast dim: same-t blocks adjacent)
    const int t   = blockIdx.y;         // 0..255
    const int tid = threadIdx.x;
    const int wid = tid >> 5;           // 0..7 == bl
    const int lid = tid & 31;
    const int b0  = bc * BPB;

    // ---- adj = sigmoid(A_t) off-diag, 1 on diag; 4x float4/thread, unroll 2 ----
    const float4* Ag = reinterpret_cast<const float4*>(A + (size_t)t * VV * VV);
    #pragma unroll 2
    for (int k = 0; k < 4; ++k) {
        int i  = tid + k * NT;          // float4 index 0..1023, coalesced
        int v  = i >> 4;
        int w4 = i & 15;
        float4 a = Ag[i];
        float4 s;
        s.x = 1.0f / (1.0f + __expf(-a.x));
        s.y = 1.0f / (1.0f + __expf(-a.y));
        s.z = 1.0f / (1.0f + __expf(-a.z));
        s.w = 1.0f / (1.0f + __expf(-a.w));
        int wbase = w4 * 4;
        if (v == wbase + 0) s.x = 1.0f;
        if (v == wbase + 1) s.y = 1.0f;
        if (v == wbase + 2) s.z = 1.0f;
        if (v == wbase + 3) s.w = 1.0f;
        *reinterpret_cast<float4*>(&adj[v][wbase]) = s;
    }

    // ---- stage xs[bl][w] = X[b0+bl, w, t] ----
    #pragma unroll 2
    for (int k = 0; k < (BPB * VV) / NT; ++k) {      // 2 iters
        int i  = tid + k * NT;
        int bl = i >> 6, w = i & 63;
        xs[bl][w] = X[((size_t)(b0 + bl) * VV + w) * TT + t];
    }

    // f index per lane is invariant: p mod 16 == lid mod 16
    const float4 wv = reinterpret_cast<const float4*>(W)[lid & 15];

    __syncthreads();                    // ONLY block-wide barrier

    // ---- warp-private dot: lane owns v=lid and v+32 of row bl=wid ----
    {
        float s0 = 0.f, s1 = 0.f;
        #pragma unroll
        for (int w4 = 0; w4 < 16; ++w4) {
            float4 p = *reinterpret_cast<const float4*>(&adj[lid     ][w4 * 4]); // conflict-free
            float4 q = *reinterpret_cast<const float4*>(&adj[lid + 32][w4 * 4]); // conflict-free
            float4 x = *reinterpret_cast<const float4*>(&xs[wid][w4 * 4]);       // warp bcast
            s0 = fmaf(p.x, x.x, s0); s0 = fmaf(p.y, x.y, s0);
            s0 = fmaf(p.z, x.z, s0); s0 = fmaf(p.w, x.w, s0);
            s1 = fmaf(q.x, x.x, s1); s1 = fmaf(q.y, x.y, s1);
            s1 = fmaf(q.z, x.z, s1); s1 = fmaf(q.w, x.w, s1);
        }
        hs[wid][lid]      = s0;
        hs[wid][lid + 32] = s1;
    }
    __syncwarp();                       // warp-local visibility of hs[wid]

    // ---- warp streams its own 16 KB row; no block barrier -> de-staggered ----
    float4* o = reinterpret_cast<float4*>(
        out + ((size_t)(b0 + wid) * TT + t) * (VV * FF));
    #pragma unroll 4
    for (int j = 0; j < (VV * FF / 4) / 32; ++j) {   // 32 iters
        int p = j * 32 + lid;                        // float4 idx, coalesced per warp
        float h = hs[wid][p >> 4];                   // 2 distinct addrs/warp: bcast
        float4 r;
        r.x = h * wv.x; r.y = h * wv.y; r.z = h * wv.z; r.w = h * wv.w;
        r.x = fmaxf(r.x, 0.01f * r.x);               // leaky for both signs
        r.y = fmaxf(r.y, 0.01f * r.y);
        r.z = fmaxf(r.z, 0.01f * r.z);
        r.w = fmaxf(r.w, 0.01f * r.w);
        __stcs(&o[p], r);                            // evict-first stream
    }
}

extern "C" void kernel_launch(void* const* d_in, const int* in_sizes, int n_in,
                              void* d_out, int out_size) {
    const float* X = (const float*)d_in[0];   // [64, 64, 256]
    const float* A = (const float*)d_in[1];   // [256, 64, 64]
    const float* W = (const float*)d_in[2];   // [64, 1]
    float* out = (float*)d_out;               // [64, 256, 4096]
    (void)in_sizes; (void)n_in; (void)out_size;

    dim3 grid(BB / BPB, TT);                  // (8, 256): same-t blocks adjacent
    gnn_fused<<<grid, NT>>>(X, A, W, out);
}